// round 3
// baseline (speedup 1.0000x reference)
#include <cuda_runtime.h>
#include <cstdint>
#include <cstddef>

#define INF_F 1e12f

namespace {

constexpr int B  = 16;
constexpr int L  = 512;
constexpr int H  = 1024;
constexpr int D2 = 128;   // HEAD_SIZE*2
constexpr int D  = 64;    // HEAD_SIZE
constexpr int NH = 12;    // HEADS
constexpr int C  = 24;    // HEADS*2

// Scratch (allocation-free rule: __device__ globals)
__device__ float g_q[B * L * D];       // rope'd qw
__device__ float g_k[B * L * D];       // rope'd kw
__device__ float g_bias[B * C * L];    // (x@W2+b2)/2, layout [B][C][L]
__device__ float g_sin[L * 32];
__device__ float g_cos[L * 32];

__device__ __forceinline__ unsigned long long pack2(float lo, float hi) {
    unsigned long long r;
    asm("mov.b64 %0, {%1, %2};" : "=l"(r) : "f"(lo), "f"(hi));
    return r;
}
__device__ __forceinline__ void unpack2(unsigned long long v, float& lo, float& hi) {
    asm("mov.b64 {%0, %1}, %2;" : "=f"(lo), "=f"(hi) : "l"(v));
}
// Packed dual-fp32 FMA (Blackwell f32x2 pipe): 2x scalar FFMA throughput.
// Scalar fallback guard in case of an unexpected arch flag on the host.
__device__ __forceinline__ unsigned long long fma2(unsigned long long a,
                                                   unsigned long long b,
                                                   unsigned long long c) {
#if !defined(__CUDA_ARCH__) || (__CUDA_ARCH__ >= 1000)
    unsigned long long d;
    asm("fma.rn.f32x2 %0, %1, %2, %3;" : "=l"(d) : "l"(a), "l"(b), "l"(c));
    return d;
#else
    float al, ah, bl, bh, cl, ch;
    unpack2(a, al, ah); unpack2(b, bl, bh); unpack2(c, cl, ch);
    return pack2(fmaf(al, bl, cl), fmaf(ah, bh, ch));
#endif
}

// ---------------------------------------------------------------------------
// Kernel 0: RoPE sin/cos tables (double-precision trig for accuracy)
// ---------------------------------------------------------------------------
__global__ __launch_bounds__(256) void rope_init_kernel() {
    int idx = blockIdx.x * 256 + threadIdx.x;   // grid covers exactly L*32
    int l = idx >> 5;
    int j = idx & 31;
    double invf = exp(-((double)(2 * j) / 64.0) * log(10000.0));
    float  freq = (float)l * (float)invf;   // fp32 product like reference
    g_sin[idx] = (float)sin((double)freq);
    g_cos[idx] = (float)cos((double)freq);
}

// ---------------------------------------------------------------------------
// Kernel 1: x = inputs@W1 + b1 (M=8192,K=1024,N=128), fused RoPE + bias epilogue
// Block: 32 rows x 128 cols, 256 threads, f32x2 packed FMAs.
// ---------------------------------------------------------------------------
__global__ __launch_bounds__(256) void gemm1_kernel(
    const float* __restrict__ inp,   // [B*L, H]
    const float* __restrict__ W1,    // [H, D2]
    const float* __restrict__ b1,    // [D2]
    const float* __restrict__ W2,    // [D2, C]
    const float* __restrict__ b2)    // [C]
{
    __shared__ float As[32][36];     // input tile [row][k]
    __shared__ float Bs[32][128];    // W1 tile    [k][col]
    __shared__ float xs[32][132];    // x tile (with b1)

    const int tid = threadIdx.x;
    const int r0  = blockIdx.x * 32;        // global row base (b*L + l)
    const int g   = tid >> 5;               // row group 0..7 (constant per warp)
    const int c0  = (tid & 31) * 4;         // col base 0..124

    unsigned long long acc[4][2];
#pragma unroll
    for (int i = 0; i < 4; i++) { acc[i][0] = 0ull; acc[i][1] = 0ull; }

    for (int k0 = 0; k0 < H; k0 += 32) {
        {   // load As: one float4 per thread (coalesced)
            int r = tid >> 3, kq = tid & 7;
            *(float4*)&As[r][kq * 4] =
                *(const float4*)(inp + (size_t)(r0 + r) * H + k0 + kq * 4);
        }
#pragma unroll
        for (int i = 0; i < 4; i++) {        // load Bs: 4 float4 per thread
            int f = tid + 256 * i;           // 0..1023
            int k = f >> 5, c4 = f & 31;
            *(float4*)&Bs[k][c4 * 4] =
                *(const float4*)(W1 + (size_t)(k0 + k) * D2 + c4 * 4);
        }
        __syncthreads();
#pragma unroll
        for (int kk = 0; kk < 32; kk++) {
            ulonglong2 bv = *(ulonglong2*)&Bs[kk][c0];
#pragma unroll
            for (int i = 0; i < 4; i++) {
                float a = As[g * 4 + i][kk];          // broadcast within warp
                unsigned long long a2 = pack2(a, a);
                acc[i][0] = fma2(a2, bv.x, acc[i][0]);
                acc[i][1] = fma2(a2, bv.y, acc[i][1]);
            }
        }
        __syncthreads();
    }

    // stage x (+b1) into smem
    float b1v0 = b1[c0], b1v1 = b1[c0 + 1], b1v2 = b1[c0 + 2], b1v3 = b1[c0 + 3];
#pragma unroll
    for (int i = 0; i < 4; i++) {
        float x0, x1, x2, x3;
        unpack2(acc[i][0], x0, x1);
        unpack2(acc[i][1], x2, x3);
        int r = g * 4 + i;
        xs[r][c0 + 0] = x0 + b1v0;
        xs[r][c0 + 1] = x1 + b1v1;
        xs[r][c0 + 2] = x2 + b1v2;
        xs[r][c0 + 3] = x3 + b1v3;
    }
    __syncthreads();

    const int b  = r0 / L;
    const int p0 = r0 % L;

    // RoPE: qw[d]=x[2d], kw[d]=x[2d+1]; pairs (x[4j],x[4j+2]) and (x[4j+1],x[4j+3])
#pragma unroll
    for (int t = tid; t < 32 * 32; t += 256) {
        int row = t >> 5, j = t & 31;
        int pos = p0 + row;
        float s  = g_sin[pos * 32 + j];
        float cw = g_cos[pos * 32 + j];
        float x0 = xs[row][4 * j + 0];
        float x1 = xs[row][4 * j + 1];
        float x2 = xs[row][4 * j + 2];
        float x3 = xs[row][4 * j + 3];
        float2 qv = make_float2(x0 * cw - x2 * s, x0 * s + x2 * cw);
        float2 kv = make_float2(x1 * cw - x3 * s, x1 * s + x3 * cw);
        size_t off = (size_t)(r0 + row) * D + 2 * j;
        *(float2*)(g_q + off) = qv;
        *(float2*)(g_k + off) = kv;
    }

    // bias[b][c][pos] = (x . W2[:,c] + b2[c]) * 0.5
    for (int t = tid; t < 32 * C; t += 256) {
        int row = t / C, c = t % C;
        float sum = b2[c];
#pragma unroll 8
        for (int j = 0; j < D2; j++) sum += xs[row][j] * W2[j * C + c];
        g_bias[((size_t)b * C + c) * L + p0 + row] = sum * 0.5f;
    }
}

// ---------------------------------------------------------------------------
// Kernel 2: logits. Tile 16(m) x 128(n) per block, qk computed once,
// 12 heads fanned out with biases + masks. HBM-write bound.
// ---------------------------------------------------------------------------
__global__ __launch_bounds__(256) void logits_kernel(
    const float* __restrict__ am,   // [B, L]
    float* __restrict__ out)        // [B, NH, L, L]
{
    __shared__ float qs[16][68];     // [m][k]
    __shared__ float kws[64][132];   // transposed: [k][n]
    __shared__ float cbs[NH][128];   // col bias per head
    __shared__ float rbs[NH][16];    // row bias per head
    __shared__ float amn[128];
    __shared__ float amm[16];

    const int tid = threadIdx.x;
    const int n0  = blockIdx.x * 128;
    const int m0  = blockIdx.y * 16;
    const int b   = blockIdx.z;

    {   // q tile: 16x64
        int m = tid >> 4, k4 = (tid & 15) * 4;
        *(float4*)&qs[m][k4] =
            *(const float4*)(g_q + (size_t)(b * L + m0 + m) * D + k4);
    }
#pragma unroll
    for (int i = 0; i < 8; i++) {   // k tile transposed: 128x64 -> [k][n]
        int f = tid + 256 * i;      // 0..2047
        int n = f >> 4, k4 = (f & 15) * 4;
        float4 v = *(const float4*)(g_k + (size_t)(b * L + n0 + n) * D + k4);
        kws[k4 + 0][n] = v.x;
        kws[k4 + 1][n] = v.y;
        kws[k4 + 2][n] = v.z;
        kws[k4 + 3][n] = v.w;
    }
#pragma unroll
    for (int i = 0; i < 6; i++) {   // col biases: 12*128
        int t = tid + 256 * i;
        int h = t >> 7, nn = t & 127;
        cbs[h][nn] = g_bias[((size_t)b * C + 2 * h) * L + n0 + nn];
    }
    if (tid < NH * 16) {            // row biases
        int h = tid >> 4, mm = tid & 15;
        rbs[h][mm] = g_bias[((size_t)b * C + 2 * h + 1) * L + m0 + mm];
    }
    if (tid < 128) amn[tid] = am[b * L + n0 + tid];
    if (tid < 16)  amm[tid] = am[b * L + m0 + tid];
    __syncthreads();

    const int nl = (tid & 31) * 4;  // local n base
    const int mr = tid >> 5;        // 0..7; m = mr + 8*i

    unsigned long long acc[2][2] = {{0ull, 0ull}, {0ull, 0ull}};
#pragma unroll
    for (int k = 0; k < D; k += 2) {
        ulonglong2 kv0 = *(ulonglong2*)&kws[k][nl];
        ulonglong2 kv1 = *(ulonglong2*)&kws[k + 1][nl];
#pragma unroll
        for (int i = 0; i < 2; i++) {
            int m = mr + 8 * i;
            float2 qv = *(float2*)&qs[m][k];        // broadcast within warp
            unsigned long long a0 = pack2(qv.x, qv.x);
            unsigned long long a1 = pack2(qv.y, qv.y);
            acc[i][0] = fma2(a0, kv0.x, acc[i][0]);
            acc[i][1] = fma2(a0, kv0.y, acc[i][1]);
            acc[i][0] = fma2(a1, kv1.x, acc[i][0]);
            acc[i][1] = fma2(a1, kv1.y, acc[i][1]);
        }
    }

#pragma unroll
    for (int i = 0; i < 2; i++) {
        int m  = mr + 8 * i;
        int mg = m0 + m;
        float qk0, qk1, qk2, qk3;
        unpack2(acc[i][0], qk0, qk1);
        unpack2(acc[i][1], qk2, qk3);
        float base0 = qk0 * 0.125f;
        float base1 = qk1 * 0.125f;
        float base2 = qk2 * 0.125f;
        float base3 = qk3 * 0.125f;
        float am_m = amm[m];
        float pen0 = (1.0f - am_m * amn[nl + 0]) * INF_F + ((n0 + nl + 0 < mg) ? INF_F : 0.0f);
        float pen1 = (1.0f - am_m * amn[nl + 1]) * INF_F + ((n0 + nl + 1 < mg) ? INF_F : 0.0f);
        float pen2 = (1.0f - am_m * amn[nl + 2]) * INF_F + ((n0 + nl + 2 < mg) ? INF_F : 0.0f);
        float pen3 = (1.0f - am_m * amn[nl + 3]) * INF_F + ((n0 + nl + 3 < mg) ? INF_F : 0.0f);
#pragma unroll
        for (int h = 0; h < NH; h++) {
            float rb = rbs[h][m];
            float4 v;
            v.x = base0 + cbs[h][nl + 0] + rb - pen0;
            v.y = base1 + cbs[h][nl + 1] + rb - pen1;
            v.z = base2 + cbs[h][nl + 2] + rb - pen2;
            v.w = base3 + cbs[h][nl + 3] + rb - pen3;
            size_t off = (((size_t)(b * NH + h) * L + mg)) * L + n0 + nl;
            __stcs((float4*)(out + off), v);
        }
    }
}

} // anonymous namespace

// ---------------------------------------------------------------------------
extern "C" void kernel_launch(void* const* d_in, const int* in_sizes, int n_in,
                              void* d_out, int out_size) {
    const float* inputs = (const float*)d_in[0];   // [16,512,1024]
    const float* attn   = (const float*)d_in[1];   // [16,512]
    const float* W1     = (const float*)d_in[2];   // [1024,128]
    const float* b1     = (const float*)d_in[3];   // [128]
    const float* W2     = (const float*)d_in[4];   // [128,24]
    const float* b2     = (const float*)d_in[5];   // [24]
    float* out = (float*)d_out;                    // [16,12,512,512]

    rope_init_kernel<<<(L * 32) / 256, 256>>>();
    gemm1_kernel<<<(B * L) / 32, 256>>>(inputs, W1, b1, W2, b2);
    logits_kernel<<<dim3(L / 128, L / 16, B), 256>>>(attn, out);
}

// round 5
// speedup vs baseline: 1.5800x; 1.5800x over previous
#include <cuda_runtime.h>
#include <cuda_bf16.h>
#include <cstdint>
#include <cstddef>

#define INF_F 1e12f

namespace {

constexpr int B  = 16;
constexpr int L  = 512;
constexpr int H  = 1024;
constexpr int D2 = 128;   // HEAD_SIZE*2
constexpr int D  = 64;    // HEAD_SIZE
constexpr int NH = 12;    // HEADS
constexpr int C  = 24;    // HEADS*2

// Scratch (allocation-free rule: __device__ globals)
__device__ float g_q[B * L * D];       // rope'd qw (fp32)
__device__ float g_k[B * L * D];       // rope'd kw (fp32)
__device__ float g_bias[B * C * L];    // (x@W2+b2)/2, layout [B][C][L]

// ---------------------------------------------------------------------------
// helpers
// ---------------------------------------------------------------------------
__device__ __forceinline__ uint32_t smem_u32(const void* p) {
    uint32_t a;
    asm("{ .reg .u64 t; cvta.to.shared.u64 t, %1; cvt.u32.u64 %0, t; }"
        : "=r"(a) : "l"(p));
    return a;
}

__device__ __forceinline__ unsigned long long pack2(float lo, float hi) {
    unsigned long long r;
    asm("mov.b64 %0, {%1, %2};" : "=l"(r) : "f"(lo), "f"(hi));
    return r;
}
__device__ __forceinline__ void unpack2(unsigned long long v, float& lo, float& hi) {
    asm("mov.b64 {%0, %1}, %2;" : "=f"(lo), "=f"(hi) : "l"(v));
}
__device__ __forceinline__ unsigned long long fma2(unsigned long long a,
                                                   unsigned long long b,
                                                   unsigned long long c) {
    unsigned long long d;
    asm("fma.rn.f32x2 %0, %1, %2, %3;" : "=l"(d) : "l"(a), "l"(b), "l"(c));
    return d;
}

__device__ __forceinline__ void ldm_x4(uint32_t& r0, uint32_t& r1,
                                       uint32_t& r2, uint32_t& r3, uint32_t addr) {
    asm volatile("ldmatrix.sync.aligned.m8n8.x4.shared.b16 {%0,%1,%2,%3}, [%4];"
                 : "=r"(r0), "=r"(r1), "=r"(r2), "=r"(r3) : "r"(addr));
}
__device__ __forceinline__ void ldm_x4_t(uint32_t& r0, uint32_t& r1,
                                         uint32_t& r2, uint32_t& r3, uint32_t addr) {
    asm volatile("ldmatrix.sync.aligned.m8n8.x4.trans.shared.b16 {%0,%1,%2,%3}, [%4];"
                 : "=r"(r0), "=r"(r1), "=r"(r2), "=r"(r3) : "r"(addr));
}
__device__ __forceinline__ void mma_bf16(float* c,
                                         uint32_t a0, uint32_t a1, uint32_t a2, uint32_t a3,
                                         uint32_t b0, uint32_t b1) {
    asm volatile("mma.sync.aligned.m16n8k16.row.col.f32.bf16.bf16.f32 "
                 "{%0,%1,%2,%3}, {%4,%5,%6,%7}, {%8,%9}, {%0,%1,%2,%3};"
                 : "+f"(c[0]), "+f"(c[1]), "+f"(c[2]), "+f"(c[3])
                 : "r"(a0), "r"(a1), "r"(a2), "r"(a3), "r"(b0), "r"(b1));
}

__device__ __forceinline__ uint2 f4_to_bf16x4(float4 v) {
    __nv_bfloat162 a = __floats2bfloat162_rn(v.x, v.y);
    __nv_bfloat162 b = __floats2bfloat162_rn(v.z, v.w);
    uint2 r;
    r.x = *reinterpret_cast<uint32_t*>(&a);
    r.y = *reinterpret_cast<uint32_t*>(&b);
    return r;
}

// shared-memory union: mainloop buffers vs epilogue buffers
struct MainBufs {
    __nv_bfloat16 As[2][64][40];    // [buf][m][k] padded to 40 (80B rows)
    __nv_bfloat16 Bs[2][32][136];   // [buf][k][n] padded to 136 (272B rows)
};
struct EpiBufs {
    __nv_bfloat16 xs[64][132];      // x tile bf16, padded (264B rows)
    float         W2s[128][24];     // W2 copy
};

// ---------------------------------------------------------------------------
// Kernel 1: x = inputs@W1 + b1 via bf16 tensor cores, fused RoPE + bias epilog
// Block: 64 rows x 128 cols, 256 threads (8 warps: 2 m x 4 n, warp tile 32x32)
// ---------------------------------------------------------------------------
__global__ __launch_bounds__(256, 2) void gemm1_mma_kernel(
    const float* __restrict__ inp,   // [B*L, H]
    const float* __restrict__ W1,    // [H, D2]
    const float* __restrict__ b1,    // [D2]
    const float* __restrict__ W2,    // [D2, C]
    const float* __restrict__ b2)    // [C]
{
    __shared__ __align__(16) union { MainBufs m; EpiBufs e; } sm;

    const int tid  = threadIdx.x;
    const int lane = tid & 31;
    const int wid  = tid >> 5;
    const int wm   = wid & 1;         // warp m (0..1) -> 32 rows
    const int wn   = wid >> 1;        // warp n (0..3) -> 32 cols
    const int r0   = blockIdx.x * 64; // global row base

    float acc[2][4][4];
#pragma unroll
    for (int mf = 0; mf < 2; mf++)
#pragma unroll
        for (int nf = 0; nf < 4; nf++)
#pragma unroll
            for (int i = 0; i < 4; i++) acc[mf][nf][i] = 0.0f;

    // gmem load staging regs
    float4 Af0, Af1, Bf[4];
    const int a_row = tid >> 3, a_kc = (tid & 7) * 4;    // A: rows a_row, a_row+32
    const int b_kr  = tid >> 5, b_nc = (tid & 31) * 4;   // B: k rows b_kr+8i

    // prologue: chunk 0
    {
        const int k0 = 0;
        Af0 = *(const float4*)(inp + (size_t)(r0 + a_row) * H + k0 + a_kc);
        Af1 = *(const float4*)(inp + (size_t)(r0 + a_row + 32) * H + k0 + a_kc);
#pragma unroll
        for (int i = 0; i < 4; i++)
            Bf[i] = *(const float4*)(W1 + (size_t)(k0 + b_kr + 8 * i) * D2 + b_nc);
        *(uint2*)&sm.m.As[0][a_row][a_kc]      = f4_to_bf16x4(Af0);
        *(uint2*)&sm.m.As[0][a_row + 32][a_kc] = f4_to_bf16x4(Af1);
#pragma unroll
        for (int i = 0; i < 4; i++)
            *(uint2*)&sm.m.Bs[0][b_kr + 8 * i][b_nc] = f4_to_bf16x4(Bf[i]);
    }
    __syncthreads();

    const uint32_t as_base = smem_u32(&sm.m.As[0][0][0]);
    const uint32_t bs_base = smem_u32(&sm.m.Bs[0][0][0]);
    constexpr uint32_t AS_BUF = 64 * 40 * 2;   // bytes per A buffer
    constexpr uint32_t BS_BUF = 32 * 136 * 2;  // bytes per B buffer

    for (int ch = 0; ch < 32; ch++) {
        const int buf = ch & 1;
        if (ch + 1 < 32) {
            const int k0 = (ch + 1) * 32;
            Af0 = *(const float4*)(inp + (size_t)(r0 + a_row) * H + k0 + a_kc);
            Af1 = *(const float4*)(inp + (size_t)(r0 + a_row + 32) * H + k0 + a_kc);
#pragma unroll
            for (int i = 0; i < 4; i++)
                Bf[i] = *(const float4*)(W1 + (size_t)(k0 + b_kr + 8 * i) * D2 + b_nc);
        }

        // compute from smem[buf]: 2 k16 steps
#pragma unroll
        for (int ks = 0; ks < 2; ks++) {
            const int kb = ks * 16;
            uint32_t a[2][4];
#pragma unroll
            for (int mf = 0; mf < 2; mf++) {
                int row = wm * 32 + mf * 16 + (lane & 15);
                int col = kb + (lane >> 4) * 8;
                ldm_x4(a[mf][0], a[mf][1], a[mf][2], a[mf][3],
                       as_base + buf * AS_BUF + (uint32_t)(row * 80 + col * 2));
            }
            uint32_t bb[2][4];
#pragma unroll
            for (int ni = 0; ni < 2; ni++) {
                int krow = kb + (lane & 15);
                int ncol = wn * 32 + ni * 16 + (lane >> 4) * 8;
                ldm_x4_t(bb[ni][0], bb[ni][1], bb[ni][2], bb[ni][3],
                         bs_base + buf * BS_BUF + (uint32_t)(krow * 272 + ncol * 2));
            }
#pragma unroll
            for (int mf = 0; mf < 2; mf++) {
#pragma unroll
                for (int nf = 0; nf < 4; nf++) {
                    uint32_t bl = bb[nf >> 1][(nf & 1) * 2];
                    uint32_t bh = bb[nf >> 1][(nf & 1) * 2 + 1];
                    mma_bf16(acc[mf][nf], a[mf][0], a[mf][1], a[mf][2], a[mf][3], bl, bh);
                }
            }
        }

        if (ch + 1 < 32) {
            const int nb = (ch + 1) & 1;
            *(uint2*)&sm.m.As[nb][a_row][a_kc]      = f4_to_bf16x4(Af0);
            *(uint2*)&sm.m.As[nb][a_row + 32][a_kc] = f4_to_bf16x4(Af1);
#pragma unroll
            for (int i = 0; i < 4; i++)
                *(uint2*)&sm.m.Bs[nb][b_kr + 8 * i][b_nc] = f4_to_bf16x4(Bf[i]);
        }
        __syncthreads();
    }

    // ---------------- epilogue ----------------
    // (post-loop __syncthreads above guarantees all mma reads done; safe to
    //  overwrite the union with xs / W2s)
    const int b_ = r0 >> 9;      // batch
    const int p0 = r0 & 511;     // position base

    // x (+b1) -> smem bf16
#pragma unroll
    for (int nf = 0; nf < 4; nf++) {
        int c = wn * 32 + nf * 8 + (lane & 3) * 2;
        float2 b1v = *(const float2*)(b1 + c);
#pragma unroll
        for (int mf = 0; mf < 2; mf++) {
            int r_ = wm * 32 + mf * 16 + (lane >> 2);
            __nv_bfloat162 lo = __floats2bfloat162_rn(acc[mf][nf][0] + b1v.x,
                                                      acc[mf][nf][1] + b1v.y);
            __nv_bfloat162 hi = __floats2bfloat162_rn(acc[mf][nf][2] + b1v.x,
                                                      acc[mf][nf][3] + b1v.y);
            *(uint32_t*)&sm.e.xs[r_][c]     = *reinterpret_cast<uint32_t*>(&lo);
            *(uint32_t*)&sm.e.xs[r_ + 8][c] = *reinterpret_cast<uint32_t*>(&hi);
        }
    }
    // W2 -> smem
    for (int f = tid; f < 128 * 24; f += 256)
        (&sm.e.W2s[0][0])[f] = W2[f];
    __syncthreads();

    // RoPE pass: q/k fp32 to gmem, coalesced (one row per warp per iter)
    const float NEG_LOG2_1E4_OVER_32 = -13.287712379549449f / 32.0f;
#pragma unroll
    for (int it = 0; it < 8; it++) {
        int idx = tid + it * 256;
        int row = idx >> 5, j = idx & 31;
        uint2 xv = *(uint2*)&sm.e.xs[row][4 * j];
        __nv_bfloat162 p01 = *reinterpret_cast<__nv_bfloat162*>(&xv.x);
        __nv_bfloat162 p23 = *reinterpret_cast<__nv_bfloat162*>(&xv.y);
        float x0 = __bfloat162float(p01.x);
        float x1 = __bfloat162float(p01.y);
        float x2 = __bfloat162float(p23.x);
        float x3 = __bfloat162float(p23.y);
        float invf = exp2f((float)j * NEG_LOG2_1E4_OVER_32);
        float freq = (float)(p0 + row) * invf;
        float s, cw;
        __sincosf(freq, &s, &cw);
        float2 qv = make_float2(x0 * cw - x2 * s, x0 * s + x2 * cw);
        float2 kv = make_float2(x1 * cw - x3 * s, x1 * s + x3 * cw);
        size_t off = (size_t)(r0 + row) * D + 2 * j;
        *(float2*)(g_q + off) = qv;
        *(float2*)(g_k + off) = kv;
    }

    // bias pass: bias[b][c][pos] = (x . W2[:,c] + b2[c]) * 0.5
    {
        int row = tid >> 2;
        int c0  = (tid & 3) * 6;
        float accb[6];
#pragma unroll
        for (int i = 0; i < 6; i++) accb[i] = b2[c0 + i];
#pragma unroll 4
        for (int j = 0; j < 128; j++) {
            float x = __bfloat162float(sm.e.xs[row][j]);
#pragma unroll
            for (int i = 0; i < 6; i++)
                accb[i] = fmaf(x, sm.e.W2s[j][c0 + i], accb[i]);
        }
#pragma unroll
        for (int i = 0; i < 6; i++)
            g_bias[((size_t)b_ * C + c0 + i) * L + p0 + row] = accb[i] * 0.5f;
    }
}

// ---------------------------------------------------------------------------
// Kernel 2: logits. Tile 16(m) x 128(n) per block, qk computed once,
// 12 heads fanned out with biases + masks. HBM-write bound. (unchanged)
// ---------------------------------------------------------------------------
__global__ __launch_bounds__(256) void logits_kernel(
    const float* __restrict__ am,   // [B, L]
    float* __restrict__ out)        // [B, NH, L, L]
{
    __shared__ float qs[16][68];     // [m][k]
    __shared__ float kws[64][132];   // transposed: [k][n]
    __shared__ float cbs[NH][128];   // col bias per head
    __shared__ float rbs[NH][16];    // row bias per head
    __shared__ float amn[128];
    __shared__ float amm[16];

    const int tid = threadIdx.x;
    const int n0  = blockIdx.x * 128;
    const int m0  = blockIdx.y * 16;
    const int b   = blockIdx.z;

    {   // q tile: 16x64
        int m = tid >> 4, k4 = (tid & 15) * 4;
        *(float4*)&qs[m][k4] =
            *(const float4*)(g_q + (size_t)(b * L + m0 + m) * D + k4);
    }
#pragma unroll
    for (int i = 0; i < 8; i++) {   // k tile transposed: 128x64 -> [k][n]
        int f = tid + 256 * i;      // 0..2047
        int n = f >> 4, k4 = (f & 15) * 4;
        float4 v = *(const float4*)(g_k + (size_t)(b * L + n0 + n) * D + k4);
        kws[k4 + 0][n] = v.x;
        kws[k4 + 1][n] = v.y;
        kws[k4 + 2][n] = v.z;
        kws[k4 + 3][n] = v.w;
    }
#pragma unroll
    for (int i = 0; i < 6; i++) {   // col biases: 12*128
        int t = tid + 256 * i;
        int h = t >> 7, nn = t & 127;
        cbs[h][nn] = g_bias[((size_t)b * C + 2 * h) * L + n0 + nn];
    }
    if (tid < NH * 16) {            // row biases
        int h = tid >> 4, mm = tid & 15;
        rbs[h][mm] = g_bias[((size_t)b * C + 2 * h + 1) * L + m0 + mm];
    }
    if (tid < 128) amn[tid] = am[b * L + n0 + tid];
    if (tid < 16)  amm[tid] = am[b * L + m0 + tid];
    __syncthreads();

    const int nl = (tid & 31) * 4;  // local n base
    const int mr = tid >> 5;        // 0..7; m = mr + 8*i

    unsigned long long acc[2][2] = {{0ull, 0ull}, {0ull, 0ull}};
#pragma unroll
    for (int k = 0; k < D; k += 2) {
        ulonglong2 kv0 = *(ulonglong2*)&kws[k][nl];
        ulonglong2 kv1 = *(ulonglong2*)&kws[k + 1][nl];
#pragma unroll
        for (int i = 0; i < 2; i++) {
            int m = mr + 8 * i;
            float2 qv = *(float2*)&qs[m][k];        // broadcast within warp
            unsigned long long a0 = pack2(qv.x, qv.x);
            unsigned long long a1 = pack2(qv.y, qv.y);
            acc[i][0] = fma2(a0, kv0.x, acc[i][0]);
            acc[i][1] = fma2(a0, kv0.y, acc[i][1]);
            acc[i][0] = fma2(a1, kv1.x, acc[i][0]);
            acc[i][1] = fma2(a1, kv1.y, acc[i][1]);
        }
    }

#pragma unroll
    for (int i = 0; i < 2; i++) {
        int m  = mr + 8 * i;
        int mg = m0 + m;
        float qk0, qk1, qk2, qk3;
        unpack2(acc[i][0], qk0, qk1);
        unpack2(acc[i][1], qk2, qk3);
        float base0 = qk0 * 0.125f;
        float base1 = qk1 * 0.125f;
        float base2 = qk2 * 0.125f;
        float base3 = qk3 * 0.125f;
        float am_m = amm[m];
        float pen0 = (1.0f - am_m * amn[nl + 0]) * INF_F + ((n0 + nl + 0 < mg) ? INF_F : 0.0f);
        float pen1 = (1.0f - am_m * amn[nl + 1]) * INF_F + ((n0 + nl + 1 < mg) ? INF_F : 0.0f);
        float pen2 = (1.0f - am_m * amn[nl + 2]) * INF_F + ((n0 + nl + 2 < mg) ? INF_F : 0.0f);
        float pen3 = (1.0f - am_m * amn[nl + 3]) * INF_F + ((n0 + nl + 3 < mg) ? INF_F : 0.0f);
#pragma unroll
        for (int h = 0; h < NH; h++) {
            float rb = rbs[h][m];
            float4 v;
            v.x = base0 + cbs[h][nl + 0] + rb - pen0;
            v.y = base1 + cbs[h][nl + 1] + rb - pen1;
            v.z = base2 + cbs[h][nl + 2] + rb - pen2;
            v.w = base3 + cbs[h][nl + 3] + rb - pen3;
            size_t off = (((size_t)(b * NH + h) * L + mg)) * L + n0 + nl;
            __stcs((float4*)(out + off), v);
        }
    }
}

} // anonymous namespace

// ---------------------------------------------------------------------------
extern "C" void kernel_launch(void* const* d_in, const int* in_sizes, int n_in,
                              void* d_out, int out_size) {
    const float* inputs = (const float*)d_in[0];   // [16,512,1024]
    const float* attn   = (const float*)d_in[1];   // [16,512]
    const float* W1     = (const float*)d_in[2];   // [1024,128]
    const float* b1     = (const float*)d_in[3];   // [128]
    const float* W2     = (const float*)d_in[4];   // [128,24]
    const float* b2     = (const float*)d_in[5];   // [24]
    float* out = (float*)d_out;                    // [16,12,512,512]

    gemm1_mma_kernel<<<(B * L) / 64, 256>>>(inputs, W1, b1, W2, b2);
    logits_kernel<<<dim3(L / 128, L / 16, B), 256>>>(attn, out);
}

// round 8
// speedup vs baseline: 2.0326x; 1.2865x over previous
#include <cuda_runtime.h>
#include <cuda_bf16.h>
#include <cstdint>
#include <cstddef>

#define INF_F 1e12f

namespace {

constexpr int B  = 16;
constexpr int L  = 512;
constexpr int H  = 1024;
constexpr int D2 = 128;   // HEAD_SIZE*2
constexpr int D  = 64;    // HEAD_SIZE
constexpr int NH = 12;    // HEADS
constexpr int C  = 24;    // HEADS*2

// Scratch (allocation-free rule: __device__ globals)
__device__ __nv_bfloat16 g_qb[B * L * D];   // rope'd qw (bf16)
__device__ __nv_bfloat16 g_kb[B * L * D];   // rope'd kw (bf16)
__device__ float g_bias[B * C * L];         // (x@W2+b2)/2, layout [B][C][L]

// ---------------------------------------------------------------------------
// helpers
// ---------------------------------------------------------------------------
__device__ __forceinline__ uint32_t smem_u32(const void* p) {
    uint32_t a;
    asm("{ .reg .u64 t; cvta.to.shared.u64 t, %1; cvt.u32.u64 %0, t; }"
        : "=r"(a) : "l"(p));
    return a;
}
__device__ __forceinline__ void ldm_x4(uint32_t& r0, uint32_t& r1,
                                       uint32_t& r2, uint32_t& r3, uint32_t addr) {
    asm volatile("ldmatrix.sync.aligned.m8n8.x4.shared.b16 {%0,%1,%2,%3}, [%4];"
                 : "=r"(r0), "=r"(r1), "=r"(r2), "=r"(r3) : "r"(addr));
}
__device__ __forceinline__ void ldm_x4_t(uint32_t& r0, uint32_t& r1,
                                         uint32_t& r2, uint32_t& r3, uint32_t addr) {
    asm volatile("ldmatrix.sync.aligned.m8n8.x4.trans.shared.b16 {%0,%1,%2,%3}, [%4];"
                 : "=r"(r0), "=r"(r1), "=r"(r2), "=r"(r3) : "r"(addr));
}
__device__ __forceinline__ void mma_bf16(float* c,
                                         uint32_t a0, uint32_t a1, uint32_t a2, uint32_t a3,
                                         uint32_t b0, uint32_t b1) {
    asm volatile("mma.sync.aligned.m16n8k16.row.col.f32.bf16.bf16.f32 "
                 "{%0,%1,%2,%3}, {%4,%5,%6,%7}, {%8,%9}, {%0,%1,%2,%3};"
                 : "+f"(c[0]), "+f"(c[1]), "+f"(c[2]), "+f"(c[3])
                 : "r"(a0), "r"(a1), "r"(a2), "r"(a3), "r"(b0), "r"(b1));
}
__device__ __forceinline__ uint2 f4_to_bf16x4(float4 v) {
    __nv_bfloat162 a = __floats2bfloat162_rn(v.x, v.y);
    __nv_bfloat162 b = __floats2bfloat162_rn(v.z, v.w);
    uint2 r;
    r.x = *reinterpret_cast<uint32_t*>(&a);
    r.y = *reinterpret_cast<uint32_t*>(&b);
    return r;
}

// shared-memory union for gemm1: mainloop buffers vs epilogue buffers
struct MainBufs {
    __nv_bfloat16 As[2][64][40];    // [buf][m][k] padded to 40 (80B rows)
    __nv_bfloat16 Bs[2][32][136];   // [buf][k][n] padded to 136 (272B rows)
};
struct EpiBufs {
    __nv_bfloat16 xs[64][132];      // x tile bf16, padded (264B rows)
    float         W2s[128][24];     // W2 copy
};

// ---------------------------------------------------------------------------
// Kernel 1: x = inputs@W1 + b1 via bf16 tensor cores, fused RoPE + bias epilog
// Block: 64 rows x 128 cols, 256 threads (8 warps: 2 m x 4 n, warp tile 32x32)
// ---------------------------------------------------------------------------
__global__ __launch_bounds__(256, 2) void gemm1_mma_kernel(
    const float* __restrict__ inp,   // [B*L, H]
    const float* __restrict__ W1,    // [H, D2]
    const float* __restrict__ b1,    // [D2]
    const float* __restrict__ W2,    // [D2, C]
    const float* __restrict__ b2)    // [C]
{
    __shared__ __align__(16) union { MainBufs m; EpiBufs e; } sm;

    const int tid  = threadIdx.x;
    const int lane = tid & 31;
    const int wid  = tid >> 5;
    const int wm   = wid & 1;         // warp m (0..1) -> 32 rows
    const int wn   = wid >> 1;        // warp n (0..3) -> 32 cols
    const int r0   = blockIdx.x * 64; // global row base

    float acc[2][4][4];
#pragma unroll
    for (int mf = 0; mf < 2; mf++)
#pragma unroll
        for (int nf = 0; nf < 4; nf++)
#pragma unroll
            for (int i = 0; i < 4; i++) acc[mf][nf][i] = 0.0f;

    float4 Af0, Af1, Bf[4];
    const int a_row = tid >> 3, a_kc = (tid & 7) * 4;
    const int b_kr  = tid >> 5, b_nc = (tid & 31) * 4;

    {
        const int k0 = 0;
        Af0 = *(const float4*)(inp + (size_t)(r0 + a_row) * H + k0 + a_kc);
        Af1 = *(const float4*)(inp + (size_t)(r0 + a_row + 32) * H + k0 + a_kc);
#pragma unroll
        for (int i = 0; i < 4; i++)
            Bf[i] = *(const float4*)(W1 + (size_t)(k0 + b_kr + 8 * i) * D2 + b_nc);
        *(uint2*)&sm.m.As[0][a_row][a_kc]      = f4_to_bf16x4(Af0);
        *(uint2*)&sm.m.As[0][a_row + 32][a_kc] = f4_to_bf16x4(Af1);
#pragma unroll
        for (int i = 0; i < 4; i++)
            *(uint2*)&sm.m.Bs[0][b_kr + 8 * i][b_nc] = f4_to_bf16x4(Bf[i]);
    }
    __syncthreads();

    const uint32_t as_base = smem_u32(&sm.m.As[0][0][0]);
    const uint32_t bs_base = smem_u32(&sm.m.Bs[0][0][0]);
    constexpr uint32_t AS_BUF = 64 * 40 * 2;
    constexpr uint32_t BS_BUF = 32 * 136 * 2;

    for (int ch = 0; ch < 32; ch++) {
        const int buf = ch & 1;
        if (ch + 1 < 32) {
            const int k0 = (ch + 1) * 32;
            Af0 = *(const float4*)(inp + (size_t)(r0 + a_row) * H + k0 + a_kc);
            Af1 = *(const float4*)(inp + (size_t)(r0 + a_row + 32) * H + k0 + a_kc);
#pragma unroll
            for (int i = 0; i < 4; i++)
                Bf[i] = *(const float4*)(W1 + (size_t)(k0 + b_kr + 8 * i) * D2 + b_nc);
        }
#pragma unroll
        for (int ks = 0; ks < 2; ks++) {
            const int kb = ks * 16;
            uint32_t a[2][4];
#pragma unroll
            for (int mf = 0; mf < 2; mf++) {
                int row = wm * 32 + mf * 16 + (lane & 15);
                int col = kb + (lane >> 4) * 8;
                ldm_x4(a[mf][0], a[mf][1], a[mf][2], a[mf][3],
                       as_base + buf * AS_BUF + (uint32_t)(row * 80 + col * 2));
            }
            uint32_t bb[2][4];
#pragma unroll
            for (int ni = 0; ni < 2; ni++) {
                int krow = kb + (lane & 15);
                int ncol = wn * 32 + ni * 16 + (lane >> 4) * 8;
                ldm_x4_t(bb[ni][0], bb[ni][1], bb[ni][2], bb[ni][3],
                         bs_base + buf * BS_BUF + (uint32_t)(krow * 272 + ncol * 2));
            }
#pragma unroll
            for (int mf = 0; mf < 2; mf++) {
#pragma unroll
                for (int nf = 0; nf < 4; nf++) {
                    uint32_t bl = bb[nf >> 1][(nf & 1) * 2];
                    uint32_t bh = bb[nf >> 1][(nf & 1) * 2 + 1];
                    mma_bf16(acc[mf][nf], a[mf][0], a[mf][1], a[mf][2], a[mf][3], bl, bh);
                }
            }
        }
        if (ch + 1 < 32) {
            const int nb = (ch + 1) & 1;
            *(uint2*)&sm.m.As[nb][a_row][a_kc]      = f4_to_bf16x4(Af0);
            *(uint2*)&sm.m.As[nb][a_row + 32][a_kc] = f4_to_bf16x4(Af1);
#pragma unroll
            for (int i = 0; i < 4; i++)
                *(uint2*)&sm.m.Bs[nb][b_kr + 8 * i][b_nc] = f4_to_bf16x4(Bf[i]);
        }
        __syncthreads();
    }

    // ---------------- epilogue ----------------
    const int b_ = r0 >> 9;
    const int p0 = r0 & 511;

    // x (+b1) -> smem bf16
#pragma unroll
    for (int nf = 0; nf < 4; nf++) {
        int c = wn * 32 + nf * 8 + (lane & 3) * 2;
        float2 b1v = *(const float2*)(b1 + c);
#pragma unroll
        for (int mf = 0; mf < 2; mf++) {
            int r_ = wm * 32 + mf * 16 + (lane >> 2);
            __nv_bfloat162 lo = __floats2bfloat162_rn(acc[mf][nf][0] + b1v.x,
                                                      acc[mf][nf][1] + b1v.y);
            __nv_bfloat162 hi = __floats2bfloat162_rn(acc[mf][nf][2] + b1v.x,
                                                      acc[mf][nf][3] + b1v.y);
            *(uint32_t*)&sm.e.xs[r_][c]     = *reinterpret_cast<uint32_t*>(&lo);
            *(uint32_t*)&sm.e.xs[r_ + 8][c] = *reinterpret_cast<uint32_t*>(&hi);
        }
    }
    for (int f = tid; f < 128 * 24; f += 256)
        (&sm.e.W2s[0][0])[f] = W2[f];
    __syncthreads();

    // RoPE pass -> bf16 q/k
    const float NEG_LOG2_1E4_OVER_32 = -13.287712379549449f / 32.0f;
#pragma unroll
    for (int it = 0; it < 8; it++) {
        int idx = tid + it * 256;
        int row = idx >> 5, j = idx & 31;
        uint2 xv = *(uint2*)&sm.e.xs[row][4 * j];
        __nv_bfloat162 p01 = *reinterpret_cast<__nv_bfloat162*>(&xv.x);
        __nv_bfloat162 p23 = *reinterpret_cast<__nv_bfloat162*>(&xv.y);
        float x0 = __bfloat162float(p01.x);
        float x1 = __bfloat162float(p01.y);
        float x2 = __bfloat162float(p23.x);
        float x3 = __bfloat162float(p23.y);
        float invf = exp2f((float)j * NEG_LOG2_1E4_OVER_32);
        float freq = (float)(p0 + row) * invf;
        float s, cw;
        __sincosf(freq, &s, &cw);
        __nv_bfloat162 qp = __floats2bfloat162_rn(x0 * cw - x2 * s, x0 * s + x2 * cw);
        __nv_bfloat162 kp = __floats2bfloat162_rn(x1 * cw - x3 * s, x1 * s + x3 * cw);
        size_t off = (size_t)(r0 + row) * D + 2 * j;
        *(uint32_t*)&g_qb[off] = *reinterpret_cast<uint32_t*>(&qp);
        *(uint32_t*)&g_kb[off] = *reinterpret_cast<uint32_t*>(&kp);
    }

    // bias pass
    {
        int row = tid >> 2;
        int c0  = (tid & 3) * 6;
        float accb[6];
#pragma unroll
        for (int i = 0; i < 6; i++) accb[i] = b2[c0 + i];
#pragma unroll 4
        for (int j = 0; j < 128; j++) {
            float x = __bfloat162float(sm.e.xs[row][j]);
#pragma unroll
            for (int i = 0; i < 6; i++)
                accb[i] = fmaf(x, sm.e.W2s[j][c0 + i], accb[i]);
        }
#pragma unroll
        for (int i = 0; i < 6; i++)
            g_bias[((size_t)b_ * C + c0 + i) * L + p0 + row] = accb[i] * 0.5f;
    }
}

// ---------------------------------------------------------------------------
// Kernel 2 (v2): logits. Tile 32m x 128n, qk via bf16 mma, register-resident
// fan-out. 256 threads, 64-reg cap -> 4 blocks/SM.
// ---------------------------------------------------------------------------
struct LogitsMain {
    __nv_bfloat16 q[32][72];     // [m][d], rows 144B
    __nv_bfloat16 kd[64][136];   // [d][n] transposed, rows 272B
};
union LogitsSm {
    LogitsMain m;
    float qk[32][132];           // qk/8 staging, rows 528B
};

__global__ __launch_bounds__(256, 4) void logits_kernel(
    const float* __restrict__ am,   // [B, L]
    float* __restrict__ out)        // [B, NH, L, L]
{
    __shared__ __align__(16) LogitsSm ls;
    __shared__ float cbs[NH][128];
    __shared__ float rbs[NH][32];
    __shared__ float amn[128];
    __shared__ float amm[32];

    const int tid  = threadIdx.x;
    const int lane = tid & 31;
    const int w    = tid >> 5;         // warp 0..7
    const int n0   = blockIdx.x * 128;
    const int m0   = blockIdx.y * 32;
    const int b    = blockIdx.z;

    {   // q tile: 32 x 64 bf16, one uint4 per thread
        int row = tid >> 3, seg = (tid & 7) * 8;
        *(uint4*)&ls.m.q[row][seg] =
            *(const uint4*)(g_qb + (size_t)(b * L + m0 + row) * D + seg);
    }
#pragma unroll
    for (int i = 0; i < 8; i++) {   // k tile transposed: [n][d] -> [d][n]
        int f = tid + 256 * i;      // 0..2047
        int n = f >> 4, d4 = (f & 15) * 4;
        uint2 v = *(const uint2*)(g_kb + (size_t)(b * L + n0 + n) * D + d4);
        const __nv_bfloat16* p = reinterpret_cast<const __nv_bfloat16*>(&v);
        ls.m.kd[d4 + 0][n] = p[0];
        ls.m.kd[d4 + 1][n] = p[1];
        ls.m.kd[d4 + 2][n] = p[2];
        ls.m.kd[d4 + 3][n] = p[3];
    }
#pragma unroll
    for (int i = 0; i < 6; i++) {   // col biases: 12*128
        int t = tid + 256 * i;
        int h = t >> 7, nn = t & 127;
        cbs[h][nn] = g_bias[((size_t)b * C + 2 * h) * L + n0 + nn];
    }
    for (int t = tid; t < NH * 32; t += 256) {   // row biases: 12*32
        int h = t >> 5, mm = t & 31;
        rbs[h][mm] = g_bias[((size_t)b * C + 2 * h + 1) * L + m0 + mm];
    }
    if (tid < 128) amn[tid] = am[b * L + n0 + tid];
    if (tid < 32)  amm[tid] = am[b * L + m0 + tid];
    __syncthreads();

    // ---- qk via bf16 mma: warp w covers n in [w*16, w*16+16), all 32 m ----
    float acc[2][2][4];
#pragma unroll
    for (int mf = 0; mf < 2; mf++)
#pragma unroll
        for (int nf = 0; nf < 2; nf++)
#pragma unroll
            for (int i = 0; i < 4; i++) acc[mf][nf][i] = 0.0f;

    const uint32_t qbase = smem_u32(&ls.m.q[0][0]);
    const uint32_t kbase = smem_u32(&ls.m.kd[0][0]);
#pragma unroll
    for (int kk = 0; kk < 4; kk++) {
        uint32_t a[2][4];
#pragma unroll
        for (int mf = 0; mf < 2; mf++) {
            int row = mf * 16 + (lane & 15);
            int col = kk * 16 + (lane >> 4) * 8;
            ldm_x4(a[mf][0], a[mf][1], a[mf][2], a[mf][3],
                   qbase + (uint32_t)(row * 144 + col * 2));
        }
        uint32_t bb[4];
        {
            int krow = kk * 16 + (lane & 15);
            int ncol = w * 16 + (lane >> 4) * 8;
            ldm_x4_t(bb[0], bb[1], bb[2], bb[3],
                     kbase + (uint32_t)(krow * 272 + ncol * 2));
        }
#pragma unroll
        for (int mf = 0; mf < 2; mf++)
#pragma unroll
            for (int nf = 0; nf < 2; nf++)
                mma_bf16(acc[mf][nf], a[mf][0], a[mf][1], a[mf][2], a[mf][3],
                         bb[nf * 2], bb[nf * 2 + 1]);
    }
    __syncthreads();   // all q/kd reads done before union overwrite

    // stage qk/8 to smem
#pragma unroll
    for (int mf = 0; mf < 2; mf++) {
#pragma unroll
        for (int nf = 0; nf < 2; nf++) {
            int row = mf * 16 + (lane >> 2);
            int col = w * 16 + nf * 8 + (lane & 3) * 2;
            ls.qk[row][col]         = acc[mf][nf][0] * 0.125f;
            ls.qk[row][col + 1]     = acc[mf][nf][1] * 0.125f;
            ls.qk[row + 8][col]     = acc[mf][nf][2] * 0.125f;
            ls.qk[row + 8][col + 1] = acc[mf][nf][3] * 0.125f;
        }
    }
    __syncthreads();

    // ---- fan-out: thread = (mr rows {mr,mr+8,mr+16,mr+24}) x (4 cols) ----
    const int nl = lane * 4;
    const int mr = tid >> 5;

    float4 amn4 = *(float4*)&amn[nl];
    float base[4][4];
#pragma unroll
    for (int i = 0; i < 4; i++) {
        int m  = mr + 8 * i;
        int mg = m0 + m;
        float4 qv  = *(float4*)&ls.qk[m][nl];
        float am_m = amm[m];
        base[i][0] = qv.x - ((1.0f - am_m * amn4.x) * INF_F + ((n0 + nl + 0 < mg) ? INF_F : 0.0f));
        base[i][1] = qv.y - ((1.0f - am_m * amn4.y) * INF_F + ((n0 + nl + 1 < mg) ? INF_F : 0.0f));
        base[i][2] = qv.z - ((1.0f - am_m * amn4.z) * INF_F + ((n0 + nl + 2 < mg) ? INF_F : 0.0f));
        base[i][3] = qv.w - ((1.0f - am_m * amn4.w) * INF_F + ((n0 + nl + 3 < mg) ? INF_F : 0.0f));
    }

    const size_t off0 = ((size_t)(b * NH) * L + (m0 + mr)) * L + n0 + nl;
#pragma unroll
    for (int h = 0; h < NH; h++) {
        float4 cb = *(float4*)&cbs[h][nl];
        size_t offh = off0 + (size_t)h * L * L;
#pragma unroll
        for (int i = 0; i < 4; i++) {
            float rb = rbs[h][mr + 8 * i];
            float4 v;
            v.x = base[i][0] + cb.x + rb;
            v.y = base[i][1] + cb.y + rb;
            v.z = base[i][2] + cb.z + rb;
            v.w = base[i][3] + cb.w + rb;
            __stcs((float4*)(out + offh + (size_t)(8 * i) * L), v);
        }
    }
}

} // anonymous namespace

// ---------------------------------------------------------------------------
extern "C" void kernel_launch(void* const* d_in, const int* in_sizes, int n_in,
                              void* d_out, int out_size) {
    const float* inputs = (const float*)d_in[0];   // [16,512,1024]
    const float* attn   = (const float*)d_in[1];   // [16,512]
    const float* W1     = (const float*)d_in[2];   // [1024,128]
    const float* b1     = (const float*)d_in[3];   // [128]
    const float* W2     = (const float*)d_in[4];   // [128,24]
    const float* b2     = (const float*)d_in[5];   // [24]
    float* out = (float*)d_out;                    // [16,12,512,512]

    gemm1_mma_kernel<<<(B * L) / 64, 256>>>(inputs, W1, b1, W2, b2);
    logits_kernel<<<dim3(L / 128, L / 32, B), 256>>>(attn, out);
}

// round 10
// speedup vs baseline: 2.1567x; 1.0611x over previous
#include <cuda_runtime.h>
#include <cuda_bf16.h>
#include <cstdint>
#include <cstddef>

#define INF_F 1e12f

namespace {

constexpr int B  = 16;
constexpr int L  = 512;
constexpr int H  = 1024;
constexpr int D2 = 128;   // HEAD_SIZE*2
constexpr int D  = 64;    // HEAD_SIZE
constexpr int NH = 12;    // HEADS
constexpr int C  = 24;    // HEADS*2

// Scratch (allocation-free rule: __device__ globals)
__device__ __nv_bfloat16 g_qb[B * L * D];   // rope'd qw (bf16)
__device__ __nv_bfloat16 g_kb[B * L * D];   // rope'd kw (bf16)
__device__ float g_bias[B * C * L];         // (x@W2+b2)/2, layout [B][C][L]

// ---------------------------------------------------------------------------
// helpers
// ---------------------------------------------------------------------------
__device__ __forceinline__ uint32_t smem_u32(const void* p) {
    uint32_t a;
    asm("{ .reg .u64 t; cvta.to.shared.u64 t, %1; cvt.u32.u64 %0, t; }"
        : "=r"(a) : "l"(p));
    return a;
}
__device__ __forceinline__ void ldm_x4(uint32_t& r0, uint32_t& r1,
                                       uint32_t& r2, uint32_t& r3, uint32_t addr) {
    asm volatile("ldmatrix.sync.aligned.m8n8.x4.shared.b16 {%0,%1,%2,%3}, [%4];"
                 : "=r"(r0), "=r"(r1), "=r"(r2), "=r"(r3) : "r"(addr));
}
__device__ __forceinline__ void ldm_x4_t(uint32_t& r0, uint32_t& r1,
                                         uint32_t& r2, uint32_t& r3, uint32_t addr) {
    asm volatile("ldmatrix.sync.aligned.m8n8.x4.trans.shared.b16 {%0,%1,%2,%3}, [%4];"
                 : "=r"(r0), "=r"(r1), "=r"(r2), "=r"(r3) : "r"(addr));
}
__device__ __forceinline__ void mma_bf16(float* c,
                                         uint32_t a0, uint32_t a1, uint32_t a2, uint32_t a3,
                                         uint32_t b0, uint32_t b1) {
    asm volatile("mma.sync.aligned.m16n8k16.row.col.f32.bf16.bf16.f32 "
                 "{%0,%1,%2,%3}, {%4,%5,%6,%7}, {%8,%9}, {%0,%1,%2,%3};"
                 : "+f"(c[0]), "+f"(c[1]), "+f"(c[2]), "+f"(c[3])
                 : "r"(a0), "r"(a1), "r"(a2), "r"(a3), "r"(b0), "r"(b1));
}
__device__ __forceinline__ uint2 f4_to_bf16x4(float4 v) {
    __nv_bfloat162 a = __floats2bfloat162_rn(v.x, v.y);
    __nv_bfloat162 b = __floats2bfloat162_rn(v.z, v.w);
    uint2 r;
    r.x = *reinterpret_cast<uint32_t*>(&a);
    r.y = *reinterpret_cast<uint32_t*>(&b);
    return r;
}

// shared-memory union for gemm1 (32-row tile): mainloop vs epilogue buffers
struct MainBufs {
    __nv_bfloat16 As[2][32][40];    // [buf][m][k] padded to 40 (80B rows)
    __nv_bfloat16 Bs[2][32][136];   // [buf][k][n] padded to 136 (272B rows)
};
struct EpiBufs {
    __nv_bfloat16 xs[32][132];      // x tile bf16, padded (264B rows)
    float         W2s[128][24];     // W2 copy
};

// ---------------------------------------------------------------------------
// Kernel 1: x = inputs@W1 + b1 via bf16 tensor cores, fused RoPE + bias epilog
// Block: 32 rows x 128 cols, 256 threads (8 warps: 2 m x 4 n, warp tile 16x32)
// 256 blocks -> full wave at 4 blocks/SM (was 128 blocks, <1/SM).
// ---------------------------------------------------------------------------
__global__ __launch_bounds__(256, 4) void gemm1_mma_kernel(
    const float* __restrict__ inp,   // [B*L, H]
    const float* __restrict__ W1,    // [H, D2]
    const float* __restrict__ b1,    // [D2]
    const float* __restrict__ W2,    // [D2, C]
    const float* __restrict__ b2)    // [C]
{
    __shared__ __align__(16) union { MainBufs m; EpiBufs e; } sm;

    const int tid  = threadIdx.x;
    const int lane = tid & 31;
    const int wid  = tid >> 5;
    const int wm   = wid & 1;         // warp m (0..1) -> 16 rows
    const int wn   = wid >> 1;        // warp n (0..3) -> 32 cols
    const int r0   = blockIdx.x * 32; // global row base

    float acc[4][4];                  // [nf][frag] : 16x32 warp tile
#pragma unroll
    for (int nf = 0; nf < 4; nf++)
#pragma unroll
        for (int i = 0; i < 4; i++) acc[nf][i] = 0.0f;

    float4 Af, Bf[4];
    const int a_row = tid >> 3, a_kc = (tid & 7) * 4;    // 32 rows, 1 float4/thread
    const int b_kr  = tid >> 5, b_nc = (tid & 31) * 4;   // B: k rows b_kr+8i

    {
        const int k0 = 0;
        Af = *(const float4*)(inp + (size_t)(r0 + a_row) * H + k0 + a_kc);
#pragma unroll
        for (int i = 0; i < 4; i++)
            Bf[i] = *(const float4*)(W1 + (size_t)(k0 + b_kr + 8 * i) * D2 + b_nc);
        *(uint2*)&sm.m.As[0][a_row][a_kc] = f4_to_bf16x4(Af);
#pragma unroll
        for (int i = 0; i < 4; i++)
            *(uint2*)&sm.m.Bs[0][b_kr + 8 * i][b_nc] = f4_to_bf16x4(Bf[i]);
    }
    __syncthreads();

    const uint32_t as_base = smem_u32(&sm.m.As[0][0][0]);
    const uint32_t bs_base = smem_u32(&sm.m.Bs[0][0][0]);
    constexpr uint32_t AS_BUF = 32 * 40 * 2;
    constexpr uint32_t BS_BUF = 32 * 136 * 2;

    for (int ch = 0; ch < 32; ch++) {
        const int buf = ch & 1;
        if (ch + 1 < 32) {
            const int k0 = (ch + 1) * 32;
            Af = *(const float4*)(inp + (size_t)(r0 + a_row) * H + k0 + a_kc);
#pragma unroll
            for (int i = 0; i < 4; i++)
                Bf[i] = *(const float4*)(W1 + (size_t)(k0 + b_kr + 8 * i) * D2 + b_nc);
        }
#pragma unroll
        for (int ks = 0; ks < 2; ks++) {
            const int kb = ks * 16;
            uint32_t a[4];
            {
                int row = wm * 16 + (lane & 15);
                int col = kb + (lane >> 4) * 8;
                ldm_x4(a[0], a[1], a[2], a[3],
                       as_base + buf * AS_BUF + (uint32_t)(row * 80 + col * 2));
            }
            uint32_t bb[2][4];
#pragma unroll
            for (int ni = 0; ni < 2; ni++) {
                int krow = kb + (lane & 15);
                int ncol = wn * 32 + ni * 16 + (lane >> 4) * 8;
                ldm_x4_t(bb[ni][0], bb[ni][1], bb[ni][2], bb[ni][3],
                         bs_base + buf * BS_BUF + (uint32_t)(krow * 272 + ncol * 2));
            }
#pragma unroll
            for (int nf = 0; nf < 4; nf++) {
                uint32_t bl = bb[nf >> 1][(nf & 1) * 2];
                uint32_t bh = bb[nf >> 1][(nf & 1) * 2 + 1];
                mma_bf16(acc[nf], a[0], a[1], a[2], a[3], bl, bh);
            }
        }
        if (ch + 1 < 32) {
            const int nb = (ch + 1) & 1;
            *(uint2*)&sm.m.As[nb][a_row][a_kc] = f4_to_bf16x4(Af);
#pragma unroll
            for (int i = 0; i < 4; i++)
                *(uint2*)&sm.m.Bs[nb][b_kr + 8 * i][b_nc] = f4_to_bf16x4(Bf[i]);
        }
        __syncthreads();
    }

    // ---------------- epilogue ----------------
    const int b_ = r0 >> 9;
    const int p0 = r0 & 511;

    // x (+b1) -> smem bf16  (warp tile rows wm*16 .. wm*16+15)
#pragma unroll
    for (int nf = 0; nf < 4; nf++) {
        int c = wn * 32 + nf * 8 + (lane & 3) * 2;
        float2 b1v = *(const float2*)(b1 + c);
        int r_ = wm * 16 + (lane >> 2);
        __nv_bfloat162 lo = __floats2bfloat162_rn(acc[nf][0] + b1v.x,
                                                  acc[nf][1] + b1v.y);
        __nv_bfloat162 hi = __floats2bfloat162_rn(acc[nf][2] + b1v.x,
                                                  acc[nf][3] + b1v.y);
        *(uint32_t*)&sm.e.xs[r_][c]     = *reinterpret_cast<uint32_t*>(&lo);
        *(uint32_t*)&sm.e.xs[r_ + 8][c] = *reinterpret_cast<uint32_t*>(&hi);
    }
    for (int f = tid; f < 128 * 24; f += 256)
        (&sm.e.W2s[0][0])[f] = W2[f];
    __syncthreads();

    // RoPE pass -> bf16 q/k  (32 rows x 32 j = 1024 items / 256 thr = 4 iters)
    const float NEG_LOG2_1E4_OVER_32 = -13.287712379549449f / 32.0f;
#pragma unroll
    for (int it = 0; it < 4; it++) {
        int idx = tid + it * 256;
        int row = idx >> 5, j = idx & 31;
        uint2 xv = *(uint2*)&sm.e.xs[row][4 * j];
        __nv_bfloat162 p01 = *reinterpret_cast<__nv_bfloat162*>(&xv.x);
        __nv_bfloat162 p23 = *reinterpret_cast<__nv_bfloat162*>(&xv.y);
        float x0 = __bfloat162float(p01.x);
        float x1 = __bfloat162float(p01.y);
        float x2 = __bfloat162float(p23.x);
        float x3 = __bfloat162float(p23.y);
        float invf = exp2f((float)j * NEG_LOG2_1E4_OVER_32);
        float freq = (float)(p0 + row) * invf;
        float s, cw;
        __sincosf(freq, &s, &cw);
        __nv_bfloat162 qp = __floats2bfloat162_rn(x0 * cw - x2 * s, x0 * s + x2 * cw);
        __nv_bfloat162 kp = __floats2bfloat162_rn(x1 * cw - x3 * s, x1 * s + x3 * cw);
        size_t off = (size_t)(r0 + row) * D + 2 * j;
        *(uint32_t*)&g_qb[off] = *reinterpret_cast<uint32_t*>(&qp);
        *(uint32_t*)&g_kb[off] = *reinterpret_cast<uint32_t*>(&kp);
    }

    // bias pass: 32 rows x 24 cols; thread = (row, 3 cols)
    {
        int row = tid >> 3;
        int c0  = (tid & 7) * 3;
        float accb[3];
#pragma unroll
        for (int i = 0; i < 3; i++) accb[i] = b2[c0 + i];
#pragma unroll 4
        for (int j = 0; j < 128; j++) {
            float x = __bfloat162float(sm.e.xs[row][j]);
#pragma unroll
            for (int i = 0; i < 3; i++)
                accb[i] = fmaf(x, sm.e.W2s[j][c0 + i], accb[i]);
        }
#pragma unroll
        for (int i = 0; i < 3; i++)
            g_bias[((size_t)b_ * C + c0 + i) * L + p0 + row] = accb[i] * 0.5f;
    }
}

// ---------------------------------------------------------------------------
// Kernel 2 (v2): logits. Tile 32m x 128n, qk via bf16 mma, register-resident
// fan-out. 256 threads, 64-reg cap -> 4 blocks/SM. (unchanged from R8 pass)
// ---------------------------------------------------------------------------
struct LogitsMain {
    __nv_bfloat16 q[32][72];     // [m][d], rows 144B
    __nv_bfloat16 kd[64][136];   // [d][n] transposed, rows 272B
};
union LogitsSm {
    LogitsMain m;
    float qk[32][132];           // qk/8 staging, rows 528B
};

__global__ __launch_bounds__(256, 4) void logits_kernel(
    const float* __restrict__ am,   // [B, L]
    float* __restrict__ out)        // [B, NH, L, L]
{
    __shared__ __align__(16) LogitsSm ls;
    __shared__ float cbs[NH][128];
    __shared__ float rbs[NH][32];
    __shared__ float amn[128];
    __shared__ float amm[32];

    const int tid  = threadIdx.x;
    const int lane = tid & 31;
    const int w    = tid >> 5;         // warp 0..7
    const int n0   = blockIdx.x * 128;
    const int m0   = blockIdx.y * 32;
    const int b    = blockIdx.z;

    {   // q tile: 32 x 64 bf16, one uint4 per thread
        int row = tid >> 3, seg = (tid & 7) * 8;
        *(uint4*)&ls.m.q[row][seg] =
            *(const uint4*)(g_qb + (size_t)(b * L + m0 + row) * D + seg);
    }
#pragma unroll
    for (int i = 0; i < 8; i++) {   // k tile transposed: [n][d] -> [d][n]
        int f = tid + 256 * i;      // 0..2047
        int n = f >> 4, d4 = (f & 15) * 4;
        uint2 v = *(const uint2*)(g_kb + (size_t)(b * L + n0 + n) * D + d4);
        const __nv_bfloat16* p = reinterpret_cast<const __nv_bfloat16*>(&v);
        ls.m.kd[d4 + 0][n] = p[0];
        ls.m.kd[d4 + 1][n] = p[1];
        ls.m.kd[d4 + 2][n] = p[2];
        ls.m.kd[d4 + 3][n] = p[3];
    }
#pragma unroll
    for (int i = 0; i < 6; i++) {   // col biases: 12*128
        int t = tid + 256 * i;
        int h = t >> 7, nn = t & 127;
        cbs[h][nn] = g_bias[((size_t)b * C + 2 * h) * L + n0 + nn];
    }
    for (int t = tid; t < NH * 32; t += 256) {   // row biases: 12*32
        int h = t >> 5, mm = t & 31;
        rbs[h][mm] = g_bias[((size_t)b * C + 2 * h + 1) * L + m0 + mm];
    }
    if (tid < 128) amn[tid] = am[b * L + n0 + tid];
    if (tid < 32)  amm[tid] = am[b * L + m0 + tid];
    __syncthreads();

    // ---- qk via bf16 mma: warp w covers n in [w*16, w*16+16), all 32 m ----
    float acc[2][2][4];
#pragma unroll
    for (int mf = 0; mf < 2; mf++)
#pragma unroll
        for (int nf = 0; nf < 2; nf++)
#pragma unroll
            for (int i = 0; i < 4; i++) acc[mf][nf][i] = 0.0f;

    const uint32_t qbase = smem_u32(&ls.m.q[0][0]);
    const uint32_t kbase = smem_u32(&ls.m.kd[0][0]);
#pragma unroll
    for (int kk = 0; kk < 4; kk++) {
        uint32_t a[2][4];
#pragma unroll
        for (int mf = 0; mf < 2; mf++) {
            int row = mf * 16 + (lane & 15);
            int col = kk * 16 + (lane >> 4) * 8;
            ldm_x4(a[mf][0], a[mf][1], a[mf][2], a[mf][3],
                   qbase + (uint32_t)(row * 144 + col * 2));
        }
        uint32_t bb[4];
        {
            int krow = kk * 16 + (lane & 15);
            int ncol = w * 16 + (lane >> 4) * 8;
            ldm_x4_t(bb[0], bb[1], bb[2], bb[3],
                     kbase + (uint32_t)(krow * 272 + ncol * 2));
        }
#pragma unroll
        for (int mf = 0; mf < 2; mf++)
#pragma unroll
            for (int nf = 0; nf < 2; nf++)
                mma_bf16(acc[mf][nf], a[mf][0], a[mf][1], a[mf][2], a[mf][3],
                         bb[nf * 2], bb[nf * 2 + 1]);
    }
    __syncthreads();   // all q/kd reads done before union overwrite

    // stage qk/8 to smem
#pragma unroll
    for (int mf = 0; mf < 2; mf++) {
#pragma unroll
        for (int nf = 0; nf < 2; nf++) {
            int row = mf * 16 + (lane >> 2);
            int col = w * 16 + nf * 8 + (lane & 3) * 2;
            ls.qk[row][col]         = acc[mf][nf][0] * 0.125f;
            ls.qk[row][col + 1]     = acc[mf][nf][1] * 0.125f;
            ls.qk[row + 8][col]     = acc[mf][nf][2] * 0.125f;
            ls.qk[row + 8][col + 1] = acc[mf][nf][3] * 0.125f;
        }
    }
    __syncthreads();

    // ---- fan-out: thread = (mr rows {mr,mr+8,mr+16,mr+24}) x (4 cols) ----
    const int nl = lane * 4;
    const int mr = tid >> 5;

    float4 amn4 = *(float4*)&amn[nl];
    float base[4][4];
#pragma unroll
    for (int i = 0; i < 4; i++) {
        int m  = mr + 8 * i;
        int mg = m0 + m;
        float4 qv  = *(float4*)&ls.qk[m][nl];
        float am_m = amm[m];
        base[i][0] = qv.x - ((1.0f - am_m * amn4.x) * INF_F + ((n0 + nl + 0 < mg) ? INF_F : 0.0f));
        base[i][1] = qv.y - ((1.0f - am_m * amn4.y) * INF_F + ((n0 + nl + 1 < mg) ? INF_F : 0.0f));
        base[i][2] = qv.z - ((1.0f - am_m * amn4.z) * INF_F + ((n0 + nl + 2 < mg) ? INF_F : 0.0f));
        base[i][3] = qv.w - ((1.0f - am_m * amn4.w) * INF_F + ((n0 + nl + 3 < mg) ? INF_F : 0.0f));
    }

    const size_t off0 = ((size_t)(b * NH) * L + (m0 + mr)) * L + n0 + nl;
#pragma unroll
    for (int h = 0; h < NH; h++) {
        float4 cb = *(float4*)&cbs[h][nl];
        size_t offh = off0 + (size_t)h * L * L;
#pragma unroll
        for (int i = 0; i < 4; i++) {
            float rb = rbs[h][mr + 8 * i];
            float4 v;
            v.x = base[i][0] + cb.x + rb;
            v.y = base[i][1] + cb.y + rb;
            v.z = base[i][2] + cb.z + rb;
            v.w = base[i][3] + cb.w + rb;
            __stcs((float4*)(out + offh + (size_t)(8 * i) * L), v);
        }
    }
}

} // anonymous namespace

// ---------------------------------------------------------------------------
extern "C" void kernel_launch(void* const* d_in, const int* in_sizes, int n_in,
                              void* d_out, int out_size) {
    const float* inputs = (const float*)d_in[0];   // [16,512,1024]
    const float* attn   = (const float*)d_in[1];   // [16,512]
    const float* W1     = (const float*)d_in[2];   // [1024,128]
    const float* b1     = (const float*)d_in[3];   // [128]
    const float* W2     = (const float*)d_in[4];   // [128,24]
    const float* b2     = (const float*)d_in[5];   // [24]
    float* out = (float*)d_out;                    // [16,12,512,512]

    gemm1_mma_kernel<<<(B * L) / 32, 256>>>(inputs, W1, b1, W2, b2);
    logits_kernel<<<dim3(L / 128, L / 32, B), 256>>>(attn, out);
}